// round 1
// baseline (speedup 1.0000x reference)
#include <cuda_runtime.h>
#include <cuda_bf16.h>
#include <math.h>

// ---------------- problem constants ----------------
#define BATCH   2
#define SEQL    2048
#define MTOK    (BATCH*SEQL)      // 4096
#define DMODEL  1024
#define DINNER  2048
#define NHEADS  32
#define HEADD   64
#define NSTATE  128
#define BCCOLS  16384             // 32 heads * 512 used cols
#define XPROJ_ROWSTRIDE 513       // x_proj_w has 513 rows per head; last unused

// ---------------- scratch (device globals; no allocation allowed) ----------------
__device__ float  g_x  [(size_t)MTOK*DINNER];     // silu(x)
__device__ float  g_z  [(size_t)MTOK*DINNER];     // raw z
__device__ float  g_dt [(size_t)MTOK*NHEADS];     // softplus(dt)
__device__ float  g_bc [(size_t)MTOK*BCCOLS];     // raw BC (per-head 512 cols)
__device__ float2 g_a  [(size_t)BATCH*NHEADS*SEQL*NSTATE]; // abar
__device__ float2 g_u  [(size_t)BATCH*NHEADS*SEQL*NSTATE]; // u_in
__device__ float2 g_c  [(size_t)BATCH*NHEADS*SEQL*NSTATE]; // Cc
__device__ float  g_yred[(size_t)MTOK*NHEADS];
__device__ float  g_y  [(size_t)MTOK*DINNER];

// ---------------- helpers ----------------
__device__ __forceinline__ float siluf(float v) {
    return v / (1.0f + expf(-v));
}
__device__ __forceinline__ float softplusf(float v) {
    return (v > 20.0f) ? v : log1pf(expf(v));
}

// ---------------- generic fp32 GEMM: C = A[MxK] @ W[NxK]^T ----------------
// BM=BN=128, BK=16, 256 threads, 8x8 microtile.
// EPI 0: plain store to C0 (ldc = N)
// EPI 1: in_proj epilogue: col<DINNER -> C0 = silu(v); else C1 = v (ldc DINNER each)
// REMAP: W row index remap for x_proj (skip 513th col per head)
template<int EPI, bool REMAP>
__global__ __launch_bounds__(256, 2)
void sgemm_k(const float* __restrict__ A, const float* __restrict__ W,
             float* __restrict__ C0, float* __restrict__ C1,
             int M, int N, int K)
{
    __shared__ float As[16][128];
    __shared__ float Bs[16][128];

    const int tid = threadIdx.x;
    const int tx = tid & 15;        // 0..15 -> N dim
    const int ty = tid >> 4;        // 0..15 -> M dim
    const int m0 = blockIdx.y * 128;
    const int n0 = blockIdx.x * 128;

    float acc[8][8];
#pragma unroll
    for (int i = 0; i < 8; i++)
#pragma unroll
        for (int j = 0; j < 8; j++) acc[i][j] = 0.0f;

    for (int k0 = 0; k0 < K; k0 += 16) {
        // load A tile (128 rows x 16 cols) as 512 float4
#pragma unroll
        for (int i = 0; i < 2; i++) {
            int idx = tid + i * 256;        // 0..511
            int row = idx >> 2;
            int c4  = idx & 3;
            float4 v = *(const float4*)(A + (size_t)(m0 + row) * K + k0 + c4 * 4);
            As[c4*4+0][row] = v.x; As[c4*4+1][row] = v.y;
            As[c4*4+2][row] = v.z; As[c4*4+3][row] = v.w;
        }
        // load W tile
#pragma unroll
        for (int i = 0; i < 2; i++) {
            int idx = tid + i * 256;
            int row = idx >> 2;
            int c4  = idx & 3;
            int wr = n0 + row;
            if (REMAP) wr = (wr >> 9) * XPROJ_ROWSTRIDE + (wr & 511);
            float4 v = *(const float4*)(W + (size_t)wr * K + k0 + c4 * 4);
            Bs[c4*4+0][row] = v.x; Bs[c4*4+1][row] = v.y;
            Bs[c4*4+2][row] = v.z; Bs[c4*4+3][row] = v.w;
        }
        __syncthreads();

#pragma unroll
        for (int k = 0; k < 16; k++) {
            float a[8], b[8];
#pragma unroll
            for (int i = 0; i < 8; i++) a[i] = As[k][ty * 8 + i];
#pragma unroll
            for (int j = 0; j < 8; j++) b[j] = Bs[k][tx * 8 + j];
#pragma unroll
            for (int i = 0; i < 8; i++)
#pragma unroll
                for (int j = 0; j < 8; j++)
                    acc[i][j] = fmaf(a[i], b[j], acc[i][j]);
        }
        __syncthreads();
    }

    // epilogue
#pragma unroll
    for (int i = 0; i < 8; i++) {
        int m = m0 + ty * 8 + i;
#pragma unroll
        for (int j = 0; j < 8; j++) {
            int n = n0 + tx * 8 + j;
            float v = acc[i][j];
            if (EPI == 0) {
                C0[(size_t)m * N + n] = v;
            } else { // EPI == 1: in_proj split
                if (n < DINNER) C0[(size_t)m * DINNER + n] = siluf(v);
                else            C1[(size_t)m * DINNER + (n - DINNER)] = v;
            }
        }
    }
}

// ---------------- dt = softplus(x @ dtw^T + bias) ----------------
// block: 32 tokens x 32 heads, 1024 threads
__global__ __launch_bounds__(1024, 1)
void dt_kernel(const float* __restrict__ x, const float* __restrict__ w,
               const float* __restrict__ bias, float* __restrict__ dt)
{
    __shared__ float xs[32][33];
    __shared__ float ws[32][33];
    const int tid = threadIdx.x;
    const int tok = tid & 31;
    const int h   = tid >> 5;
    const int m0  = blockIdx.x * 32;

    float acc = 0.0f;
    const int lr = tid >> 5, lc = tid & 31;
    for (int k0 = 0; k0 < DINNER; k0 += 32) {
        xs[lr][lc] = x[(size_t)(m0 + lr) * DINNER + k0 + lc];
        ws[lr][lc] = w[(size_t)lr * DINNER + k0 + lc];
        __syncthreads();
#pragma unroll
        for (int kk = 0; kk < 32; kk++)
            acc = fmaf(xs[tok][kk], ws[h][kk], acc);
        __syncthreads();
    }
    dt[(size_t)(m0 + tok) * NHEADS + h] = softplusf(acc + bias[h]);
}

// ---------------- per-(token,head): RMS norm + discretization coeffs ----------------
__global__ __launch_bounds__(128, 8)
void prep_kernel(const float* __restrict__ A_, const float* __restrict__ nBw,
                 const float* __restrict__ nCw)
{
    const int m = blockIdx.x;          // token (b major)
    const int h = blockIdx.y;
    const int n = threadIdx.x;         // 0..127 state index
    const int b = m >> 11;
    const int t = m & 2047;

    const float2* row = (const float2*)(g_bc + (size_t)m * BCCOLS + h * 512);
    float2 Bv = row[n];
    float2 Cv = row[128 + n];

    __shared__ float red[3][128];
    red[0][n] = Bv.x * Bv.x + Bv.y * Bv.y;
    red[1][n] = Cv.x * Cv.x + Cv.y * Cv.y;
    red[2][n] = (n < HEADD) ? g_x[(size_t)m * DINNER + h * HEADD + n] : 0.0f;
    __syncthreads();
    for (int s = 64; s > 0; s >>= 1) {
        if (n < s) {
            red[0][n] += red[0][n + s];
            red[1][n] += red[1][n + s];
            red[2][n] += red[2][n + s];
        }
        __syncthreads();
    }
    const float rB = rsqrtf(red[0][0] * (1.0f / 256.0f) + 1e-6f);
    const float rC = rsqrtf(red[1][0] * (1.0f / 256.0f) + 1e-6f);
    const float xsum = red[2][0];

    float2 wB = ((const float2*)nBw)[n];
    float2 wC = ((const float2*)nCw)[n];
    float2 Bc = { Bv.x * rB * wB.x, Bv.y * rB * wB.y };
    float2 Cc = { Cv.x * rC * wC.x, Cv.y * rC * wC.y };

    const float dt = g_dt[(size_t)m * NHEADS + h];
    float2 Av = ((const float2*)A_)[h * NSTATE + n];
    const float hdt = 0.5f * dt;
    const float ztr = Av.x * hdt, zti = Av.y * hdt;
    const float dr = 1.0f - ztr, di = -zti;
    const float inv = 1.0f / (dr * dr + di * di);
    const float nr = 1.0f + ztr, ni = zti;
    float2 abar = { (nr * dr + ni * di) * inv, (ni * dr - nr * di) * inv };

    const float s = dt * xsum;
    const float pr = s * dr * inv, pi = -s * di * inv;
    float2 uin = { Bc.x * pr - Bc.y * pi, Bc.x * pi + Bc.y * pr };

    const size_t base = (((size_t)(b * NHEADS + h)) * SEQL + t) * NSTATE + n;
    g_a[base] = abar;
    g_u[base] = uin;
    g_c[base] = Cc;
}

// ---------------- sequential scan over L, parallel over (b,h,n) ----------------
__global__ __launch_bounds__(128, 1)
void scan_kernel()
{
    const int bh = blockIdx.x;          // b*32+h
    const int b = bh >> 5, h = bh & 31;
    const int n = threadIdx.x;          // state index

    const size_t base = ((size_t)bh * SEQL) * NSTATE + n;
    float hr = 0.0f, hi = 0.0f;

    __shared__ float rbuf[32][129];
    __shared__ float psum[4][32];
    const int row = n & 31, q = n >> 5;

    for (int t0 = 0; t0 < SEQL; t0 += 32) {
#pragma unroll 8
        for (int tt = 0; tt < 32; tt++) {
            size_t idx = base + (size_t)(t0 + tt) * NSTATE;
            float2 a = g_a[idx];
            float2 u = g_u[idx];
            float2 c = g_c[idx];
            float nhr = fmaf(a.x, hr, fmaf(-a.y, hi, u.x));
            float nhi = fmaf(a.x, hi, fmaf( a.y, hr, u.y));
            hr = nhr; hi = nhi;
            rbuf[tt][n] = c.x * hr - c.y * hi;
        }
        __syncthreads();
        float p = 0.0f;
#pragma unroll
        for (int i = 0; i < 32; i++) p += rbuf[row][q * 32 + i];
        psum[q][row] = p;
        __syncthreads();
        if (n < 32) {
            float v = psum[0][n] + psum[1][n] + psum[2][n] + psum[3][n];
            g_yred[(size_t)(b * SEQL + t0 + n) * NHEADS + h] = v;
        }
        __syncthreads();
    }
}

// ---------------- gate: y = x * (y_red + D) * silu(z) ----------------
__global__ __launch_bounds__(256)
void ymul_kernel(const float* __restrict__ Dv)
{
    const int i = blockIdx.x * 256 + threadIdx.x;   // over MTOK*DINNER
    const int m = i >> 11;
    const int d = i & 2047;
    const int h = d >> 6;
    const float zr = g_z[i];
    const float sz = zr / (1.0f + expf(-zr));
    g_y[i] = g_x[i] * (g_yred[(size_t)m * NHEADS + h] + Dv[h]) * sz;
}

// ---------------- launch ----------------
extern "C" void kernel_launch(void* const* d_in, const int* in_sizes, int n_in,
                              void* d_out, int out_size)
{
    const float* u        = (const float*)d_in[0];
    const float* in_w     = (const float*)d_in[1];
    const float* dtw      = (const float*)d_in[2];
    const float* dtb      = (const float*)d_in[3];
    const float* xpw      = (const float*)d_in[4];
    const float* Amat     = (const float*)d_in[5];
    const float* Dvec     = (const float*)d_in[6];
    const float* nBw      = (const float*)d_in[7];
    const float* nCw      = (const float*)d_in[8];
    const float* outw     = (const float*)d_in[9];
    float* out            = (float*)d_out;

    void *px, *pz, *pbc, *py;
    cudaGetSymbolAddress(&px,  g_x);
    cudaGetSymbolAddress(&pz,  g_z);
    cudaGetSymbolAddress(&pbc, g_bc);
    cudaGetSymbolAddress(&py,  g_y);

    // 1. in_proj + silu/split: M=4096, N=4096, K=1024
    {
        dim3 grid(4096 / 128, MTOK / 128);
        sgemm_k<1, false><<<grid, 256>>>(u, in_w, (float*)px, (float*)pz,
                                         MTOK, 2 * DINNER, DMODEL);
    }
    // 2. dt
    {
        void* pdt; cudaGetSymbolAddress(&pdt, g_dt);
        dt_kernel<<<MTOK / 32, 1024>>>((const float*)px, dtw, dtb, (float*)pdt);
    }
    // 3. x_proj (remapped to skip unused per-head column): M=4096, N=16384, K=2048
    {
        dim3 grid(BCCOLS / 128, MTOK / 128);
        sgemm_k<0, true><<<grid, 256>>>((const float*)px, xpw, (float*)pbc, nullptr,
                                        MTOK, BCCOLS, DINNER);
    }
    // 4. prep coefficients
    {
        dim3 grid(MTOK, NHEADS);
        prep_kernel<<<grid, 128>>>(Amat, nBw, nCw);
    }
    // 5. scan
    scan_kernel<<<BATCH * NHEADS, 128>>>();
    // 6. gate
    ymul_kernel<<<(MTOK * DINNER) / 256, 256>>>(Dvec);
    // 7. out_proj: M=4096, N=1024, K=2048
    {
        dim3 grid(DMODEL / 128, MTOK / 128);
        sgemm_k<0, false><<<grid, 256>>>((const float*)py, outw, out, nullptr,
                                         MTOK, DMODEL, DINNER);
    }
    (void)in_sizes; (void)n_in; (void)out_size;
}

// round 3
// speedup vs baseline: 2.6066x; 2.6066x over previous
#include <cuda_runtime.h>
#include <cuda_bf16.h>
#include <cstdint>
#include <math.h>

// ---------------- problem constants ----------------
#define BATCH   2
#define SEQL    2048
#define MTOK    (BATCH*SEQL)      // 4096
#define DMODEL  1024
#define DINNER  2048
#define NHEADS  32
#define HEADD   64
#define NSTATE  128
#define BCCOLS  16384             // 32 heads * 512 used cols
#define XPROJ_ROWSTRIDE 513       // x_proj_w has 513 rows per head; last unused

// ---------------- fp32 scratch ----------------
__device__ float  g_x  [(size_t)MTOK*DINNER];     // silu(x)
__device__ float  g_z  [(size_t)MTOK*DINNER];     // raw z
__device__ float  g_dt [(size_t)MTOK*NHEADS];     // softplus(dt)
__device__ float  g_bc [(size_t)MTOK*BCCOLS];     // raw BC (per-head 512 cols)
__device__ float2 g_a  [(size_t)BATCH*NHEADS*SEQL*NSTATE]; // abar
__device__ float2 g_u  [(size_t)BATCH*NHEADS*SEQL*NSTATE]; // u_in
__device__ float2 g_c  [(size_t)BATCH*NHEADS*SEQL*NSTATE]; // Cc
__device__ float  g_yred[(size_t)MTOK*NHEADS];
__device__ float  g_y  [(size_t)MTOK*DINNER];

// ---------------- bf16 hi/lo-split operand scratch (K' = 3K) ----------------
__device__ __nv_bfloat16 g_uA [(size_t)MTOK * 3*DMODEL];    // A' for GEMM1
__device__ __nv_bfloat16 g_w1 [(size_t)(2*DINNER) * 3*DMODEL];
__device__ __nv_bfloat16 g_xA [(size_t)MTOK * 3*DINNER];    // A' for GEMM3
__device__ __nv_bfloat16 g_w3 [(size_t)BCCOLS * 3*DINNER];  // remapped x_proj_w
__device__ __nv_bfloat16 g_yA [(size_t)MTOK * 3*DINNER];    // A' for GEMM4
__device__ __nv_bfloat16 g_w4 [(size_t)DMODEL * 3*DINNER];

// ---------------- helpers ----------------
__device__ __forceinline__ float siluf(float v) { return v / (1.0f + expf(-v)); }
__device__ __forceinline__ float softplusf(float v) { return (v > 20.0f) ? v : log1pf(expf(v)); }

__device__ __forceinline__ uint32_t smem_u32(const void* p) {
    uint32_t a;
    asm("{ .reg .u64 t; cvta.to.shared.u64 t, %1; cvt.u32.u64 %0, t; }" : "=r"(a) : "l"(p));
    return a;
}

__device__ __forceinline__ void ldsm4(uint32_t* r, uint32_t addr) {
    asm volatile("ldmatrix.sync.aligned.m8n8.x4.shared.b16 {%0,%1,%2,%3}, [%4];"
        : "=r"(r[0]), "=r"(r[1]), "=r"(r[2]), "=r"(r[3]) : "r"(addr));
}

__device__ __forceinline__ void mma16816(float* d, const uint32_t* a, uint32_t b0, uint32_t b1) {
    asm volatile("mma.sync.aligned.m16n8k16.row.col.f32.bf16.bf16.f32 "
        "{%0,%1,%2,%3}, {%4,%5,%6,%7}, {%8,%9}, {%0,%1,%2,%3};"
        : "+f"(d[0]), "+f"(d[1]), "+f"(d[2]), "+f"(d[3])
        : "r"(a[0]), "r"(a[1]), "r"(a[2]), "r"(a[3]), "r"(b0), "r"(b1));
}

#define CP_ASYNC16(dst, src) \
    asm volatile("cp.async.cg.shared.global [%0], [%1], 16;" :: "r"(dst), "l"(src) : "memory")
#define CP_COMMIT() asm volatile("cp.async.commit_group;" ::: "memory")
#define CP_WAIT1()  asm volatile("cp.async.wait_group 1;" ::: "memory")

// ================= HMMA bf16 GEMM: C[MxN] = A'[MxK3] @ W'[NxK3]^T =================
// BM=BN=128, BK=32 (bf16), 3 cp.async stages, 256 threads (8 warps, 4M x 2N),
// warp tile 32x64 via m16n8k16. fp32 accumulate.
// EPI 0: plain fp32 store (ldc = N). EPI 1: in_proj split + silu.
// CTA swizzle: 1D grid; SUP n-blocks per super-panel for L2 reuse.
template<int EPI, int SUP>
__global__ __launch_bounds__(256, 2)
void mma_gemm(const __nv_bfloat16* __restrict__ A, const __nv_bfloat16* __restrict__ W,
              float* __restrict__ C0, float* __restrict__ C1,
              int N, int K3, int mblocks)
{
    __shared__ __align__(128) char sm[3 * 16384];   // [stage][A 8KB | B 8KB]
    const uint32_t sb = smem_u32(sm);
    const int tid  = threadIdx.x;
    const int lane = tid & 31, wid = tid >> 5;
    const int wm = wid & 3, wn = wid >> 2;

    // block swizzle: bid -> (mb, nb) within n-super-panels of width SUP
    const int bid = blockIdx.x;
    const int per_super = mblocks * SUP;
    const int sup = bid / per_super;
    const int rem = bid % per_super;
    const int m0 = (rem / SUP) * 128;
    const int n0 = (sup * SUP + rem % SUP) * 128;

    const int lrow = tid >> 2;     // 0..63 (two halves: +0, +64)
    const int lkc  = tid & 3;      // 16B chunk within 64B row
    const __nv_bfloat16* gA = A + (size_t)(m0 + lrow) * K3 + lkc * 8;
    const __nv_bfloat16* gB = W + (size_t)(n0 + lrow) * K3 + lkc * 8;

    const int KT = K3 >> 5;        // K3/32

    auto load_stage = [&](int s, int kt) {
        const int koff = kt * 32;
        #pragma unroll
        for (int half = 0; half < 2; half++) {
            const int row = lrow + half * 64;
            const uint32_t swz = (uint32_t)((lkc ^ ((row >> 1) & 3)) << 4);
            const uint32_t da = sb + s * 16384 + row * 64 + swz;
            CP_ASYNC16(da,        gA + (size_t)half * 64 * K3 + koff);
            CP_ASYNC16(da + 8192, gB + (size_t)half * 64 * K3 + koff);
        }
    };

    float acc[2][8][4];
    #pragma unroll
    for (int i = 0; i < 2; i++)
        #pragma unroll
        for (int j = 0; j < 8; j++)
            #pragma unroll
            for (int q = 0; q < 4; q++) acc[i][j][q] = 0.0f;

    load_stage(0, 0); CP_COMMIT();
    load_stage(1, 1); CP_COMMIT();

    for (int kt = 0; kt < KT; kt++) {
        CP_WAIT1();
        __syncthreads();
        if (kt + 2 < KT) load_stage((kt + 2) % 3, kt + 2);
        CP_COMMIT();                       // empty group ok on tail

        const uint32_t abase = sb + (kt % 3) * 16384;
        const uint32_t bbase = abase + 8192;

        #pragma unroll
        for (int ks = 0; ks < 2; ks++) {
            uint32_t aF[2][4], bF[4][4];
            const int kc = ks * 2 + (lane >> 4);
            #pragma unroll
            for (int mt = 0; mt < 2; mt++) {
                const int row = wm * 32 + mt * 16 + (lane & 15);
                ldsm4(aF[mt], abase + row * 64 + ((kc ^ ((row >> 1) & 3)) << 4));
            }
            #pragma unroll
            for (int nbt = 0; nbt < 4; nbt++) {
                const int row = wn * 64 + nbt * 16 + (lane & 15);
                ldsm4(bF[nbt], bbase + row * 64 + ((kc ^ ((row >> 1) & 3)) << 4));
            }
            #pragma unroll
            for (int mt = 0; mt < 2; mt++)
                #pragma unroll
                for (int nbt = 0; nbt < 4; nbt++) {
                    mma16816(acc[mt][2 * nbt + 0], aF[mt], bF[nbt][0], bF[nbt][2]);
                    mma16816(acc[mt][2 * nbt + 1], aF[mt], bF[nbt][1], bF[nbt][3]);
                }
        }
    }

    // epilogue
    #pragma unroll
    for (int mt = 0; mt < 2; mt++) {
        #pragma unroll
        for (int nt = 0; nt < 8; nt++) {
            const int r = m0 + wm * 32 + mt * 16 + (lane >> 2);
            const int c = n0 + wn * 64 + nt * 8 + (lane & 3) * 2;
            const float* a4 = acc[mt][nt];
            if (EPI == 0) {
                *(float2*)(C0 + (size_t)r * N + c)       = make_float2(a4[0], a4[1]);
                *(float2*)(C0 + (size_t)(r + 8) * N + c) = make_float2(a4[2], a4[3]);
            } else {
                if (n0 < DINNER) {
                    *(float2*)(C0 + (size_t)r * DINNER + c)       = make_float2(siluf(a4[0]), siluf(a4[1]));
                    *(float2*)(C0 + (size_t)(r + 8) * DINNER + c) = make_float2(siluf(a4[2]), siluf(a4[3]));
                } else {
                    const int cc = c - DINNER;
                    *(float2*)(C1 + (size_t)r * DINNER + cc)       = make_float2(a4[0], a4[1]);
                    *(float2*)(C1 + (size_t)(r + 8) * DINNER + cc) = make_float2(a4[2], a4[3]);
                }
            }
        }
    }
}

// ============== fp32 -> bf16 hi/lo split, K' = 3K ==============
// A-pattern: [hi | lo | hi]   W-pattern: [hi | hi | lo]
template<bool APAT, bool REMAP>
__global__ __launch_bounds__(256)
void conv3_kernel(const float* __restrict__ src, __nv_bfloat16* __restrict__ dst, int K)
{
    const int c4 = (blockIdx.x * 256 + threadIdx.x) * 4;
    const int row = blockIdx.y;
    const int srow = REMAP ? ((row >> 9) * XPROJ_ROWSTRIDE + (row & 511)) : row;
    float4 v = *(const float4*)(src + (size_t)srow * K + c4);
    __nv_bfloat16 h0 = __float2bfloat16(v.x), h1 = __float2bfloat16(v.y);
    __nv_bfloat16 h2 = __float2bfloat16(v.z), h3 = __float2bfloat16(v.w);
    __nv_bfloat16 l0 = __float2bfloat16(v.x - __bfloat162float(h0));
    __nv_bfloat16 l1 = __float2bfloat16(v.y - __bfloat162float(h1));
    __nv_bfloat16 l2 = __float2bfloat16(v.z - __bfloat162float(h2));
    __nv_bfloat16 l3 = __float2bfloat16(v.w - __bfloat162float(h3));
    __nv_bfloat162 hA = {h0, h1}, hB = {h2, h3};
    __nv_bfloat162 lA = {l0, l1}, lB = {l2, l3};
    __nv_bfloat162* d0 = (__nv_bfloat162*)(dst + (size_t)row * 3 * K + c4);
    __nv_bfloat162* d1 = (__nv_bfloat162*)(dst + (size_t)row * 3 * K + K + c4);
    __nv_bfloat162* d2 = (__nv_bfloat162*)(dst + (size_t)row * 3 * K + 2 * K + c4);
    d0[0] = hA; d0[1] = hB;
    if (APAT) { d1[0] = lA; d1[1] = lB; d2[0] = hA; d2[1] = hB; }
    else      { d1[0] = hA; d1[1] = hB; d2[0] = lA; d2[1] = lB; }
}

// ---------------- dt = softplus(x @ dtw^T + bias) ----------------
__global__ __launch_bounds__(1024, 1)
void dt_kernel(const float* __restrict__ x, const float* __restrict__ w,
               const float* __restrict__ bias, float* __restrict__ dt)
{
    __shared__ float xs[32][33];
    __shared__ float ws[32][33];
    const int tid = threadIdx.x;
    const int tok = tid & 31;
    const int h   = tid >> 5;
    const int m0  = blockIdx.x * 32;

    float acc = 0.0f;
    const int lr = tid >> 5, lc = tid & 31;
    for (int k0 = 0; k0 < DINNER; k0 += 32) {
        xs[lr][lc] = x[(size_t)(m0 + lr) * DINNER + k0 + lc];
        ws[lr][lc] = w[(size_t)lr * DINNER + k0 + lc];
        __syncthreads();
#pragma unroll
        for (int kk = 0; kk < 32; kk++)
            acc = fmaf(xs[tok][kk], ws[h][kk], acc);
        __syncthreads();
    }
    dt[(size_t)(m0 + tok) * NHEADS + h] = softplusf(acc + bias[h]);
}

// ---------------- per-(token,head): RMS norm + discretization coeffs ----------------
__global__ __launch_bounds__(128, 8)
void prep_kernel(const float* __restrict__ A_, const float* __restrict__ nBw,
                 const float* __restrict__ nCw)
{
    const int m = blockIdx.x;
    const int h = blockIdx.y;
    const int n = threadIdx.x;
    const int b = m >> 11;
    const int t = m & 2047;

    const float2* row = (const float2*)(g_bc + (size_t)m * BCCOLS + h * 512);
    float2 Bv = row[n];
    float2 Cv = row[128 + n];

    __shared__ float red[3][128];
    red[0][n] = Bv.x * Bv.x + Bv.y * Bv.y;
    red[1][n] = Cv.x * Cv.x + Cv.y * Cv.y;
    red[2][n] = (n < HEADD) ? g_x[(size_t)m * DINNER + h * HEADD + n] : 0.0f;
    __syncthreads();
    for (int s = 64; s > 0; s >>= 1) {
        if (n < s) {
            red[0][n] += red[0][n + s];
            red[1][n] += red[1][n + s];
            red[2][n] += red[2][n + s];
        }
        __syncthreads();
    }
    const float rB = rsqrtf(red[0][0] * (1.0f / 256.0f) + 1e-6f);
    const float rC = rsqrtf(red[1][0] * (1.0f / 256.0f) + 1e-6f);
    const float xsum = red[2][0];

    float2 wB = ((const float2*)nBw)[n];
    float2 wC = ((const float2*)nCw)[n];
    float2 Bc = { Bv.x * rB * wB.x, Bv.y * rB * wB.y };
    float2 Cc = { Cv.x * rC * wC.x, Cv.y * rC * wC.y };

    const float dt = g_dt[(size_t)m * NHEADS + h];
    float2 Av = ((const float2*)A_)[h * NSTATE + n];
    const float hdt = 0.5f * dt;
    const float ztr = Av.x * hdt, zti = Av.y * hdt;
    const float dr = 1.0f - ztr, di = -zti;
    const float inv = 1.0f / (dr * dr + di * di);
    const float nr = 1.0f + ztr, ni = zti;
    float2 abar = { (nr * dr + ni * di) * inv, (ni * dr - nr * di) * inv };

    const float s = dt * xsum;
    const float pr = s * dr * inv, pi = -s * di * inv;
    float2 uin = { Bc.x * pr - Bc.y * pi, Bc.x * pi + Bc.y * pr };

    const size_t base = (((size_t)(b * NHEADS + h)) * SEQL + t) * NSTATE + n;
    g_a[base] = abar;
    g_u[base] = uin;
    g_c[base] = Cc;
}

// ---------------- sequential scan over L ----------------
__global__ __launch_bounds__(128, 1)
void scan_kernel()
{
    const int bh = blockIdx.x;
    const int b = bh >> 5, h = bh & 31;
    const int n = threadIdx.x;

    const size_t base = ((size_t)bh * SEQL) * NSTATE + n;
    float hr = 0.0f, hi = 0.0f;

    __shared__ float rbuf[32][129];
    __shared__ float psum[4][32];
    const int row = n & 31, q = n >> 5;

    for (int t0 = 0; t0 < SEQL; t0 += 32) {
#pragma unroll 8
        for (int tt = 0; tt < 32; tt++) {
            size_t idx = base + (size_t)(t0 + tt) * NSTATE;
            float2 a = g_a[idx];
            float2 u = g_u[idx];
            float2 c = g_c[idx];
            float nhr = fmaf(a.x, hr, fmaf(-a.y, hi, u.x));
            float nhi = fmaf(a.x, hi, fmaf( a.y, hr, u.y));
            hr = nhr; hi = nhi;
            rbuf[tt][n] = c.x * hr - c.y * hi;
        }
        __syncthreads();
        float p = 0.0f;
#pragma unroll
        for (int i = 0; i < 32; i++) p += rbuf[row][q * 32 + i];
        psum[q][row] = p;
        __syncthreads();
        if (n < 32) {
            float v = psum[0][n] + psum[1][n] + psum[2][n] + psum[3][n];
            g_yred[(size_t)(b * SEQL + t0 + n) * NHEADS + h] = v;
        }
        __syncthreads();
    }
}

// ---------------- gate: y = x * (y_red + D) * silu(z) ----------------
__global__ __launch_bounds__(256)
void ymul_kernel(const float* __restrict__ Dv)
{
    const int i = blockIdx.x * 256 + threadIdx.x;
    const int m = i >> 11;
    const int d = i & 2047;
    const int h = d >> 6;
    const float zr = g_z[i];
    const float sz = zr / (1.0f + expf(-zr));
    g_y[i] = g_x[i] * (g_yred[(size_t)m * NHEADS + h] + Dv[h]) * sz;
}

// ---------------- launch ----------------
extern "C" void kernel_launch(void* const* d_in, const int* in_sizes, int n_in,
                              void* d_out, int out_size)
{
    const float* u    = (const float*)d_in[0];
    const float* in_w = (const float*)d_in[1];
    const float* dtw  = (const float*)d_in[2];
    const float* dtb  = (const float*)d_in[3];
    const float* xpw  = (const float*)d_in[4];
    const float* Amat = (const float*)d_in[5];
    const float* Dvec = (const float*)d_in[6];
    const float* nBw  = (const float*)d_in[7];
    const float* nCw  = (const float*)d_in[8];
    const float* outw = (const float*)d_in[9];
    float* out        = (float*)d_out;

    void *px, *pz, *pbc, *py, *pdt;
    void *puA, *pw1, *pxA, *pw3, *pyA, *pw4;
    cudaGetSymbolAddress(&px,  g_x);
    cudaGetSymbolAddress(&pz,  g_z);
    cudaGetSymbolAddress(&pbc, g_bc);
    cudaGetSymbolAddress(&py,  g_y);
    cudaGetSymbolAddress(&pdt, g_dt);
    cudaGetSymbolAddress(&puA, g_uA);
    cudaGetSymbolAddress(&pw1, g_w1);
    cudaGetSymbolAddress(&pxA, g_xA);
    cudaGetSymbolAddress(&pw3, g_w3);
    cudaGetSymbolAddress(&pyA, g_yA);
    cudaGetSymbolAddress(&pw4, g_w4);

    // --- convert GEMM1 operands ---
    conv3_kernel<true,  false><<<dim3(DMODEL/1024, MTOK),     256>>>(u,    (__nv_bfloat16*)puA, DMODEL);
    conv3_kernel<false, false><<<dim3(DMODEL/1024, 2*DINNER), 256>>>(in_w, (__nv_bfloat16*)pw1, DMODEL);
    // --- GEMM1: in_proj + silu/split  (M=4096, N=4096, K3=3072) ---
    mma_gemm<1, 8><<<32 * 32, 256>>>((const __nv_bfloat16*)puA, (const __nv_bfloat16*)pw1,
                                     (float*)px, (float*)pz, 2*DINNER, 3*DMODEL, 32);
    // --- dt ---
    dt_kernel<<<MTOK/32, 1024>>>((const float*)px, dtw, dtb, (float*)pdt);
    // --- convert GEMM3 operands ---
    conv3_kernel<true,  false><<<dim3(DINNER/1024, MTOK),   256>>>((const float*)px, (__nv_bfloat16*)pxA, DINNER);
    conv3_kernel<false, true ><<<dim3(DINNER/1024, BCCOLS), 256>>>(xpw, (__nv_bfloat16*)pw3, DINNER);
    // --- GEMM3: x_proj (M=4096, N=16384, K3=6144) ---
    mma_gemm<0, 16><<<32 * 128, 256>>>((const __nv_bfloat16*)pxA, (const __nv_bfloat16*)pw3,
                                       (float*)pbc, nullptr, BCCOLS, 3*DINNER, 32);
    // --- prep + scan + gate ---
    prep_kernel<<<dim3(MTOK, NHEADS), 128>>>(Amat, nBw, nCw);
    scan_kernel<<<BATCH * NHEADS, 128>>>();
    ymul_kernel<<<(MTOK * DINNER) / 256, 256>>>(Dvec);
    // --- convert GEMM4 operands ---
    conv3_kernel<true,  false><<<dim3(DINNER/1024, MTOK),   256>>>((const float*)py, (__nv_bfloat16*)pyA, DINNER);
    conv3_kernel<false, false><<<dim3(DINNER/1024, DMODEL), 256>>>(outw, (__nv_bfloat16*)pw4, DINNER);
    // --- GEMM4: out_proj (M=4096, N=1024, K3=6144) ---
    mma_gemm<0, 8><<<32 * 8, 256>>>((const __nv_bfloat16*)pyA, (const __nv_bfloat16*)pw4,
                                    out, nullptr, DMODEL, 3*DINNER, 32);

    (void)in_sizes; (void)n_in; (void)out_size;
}